// round 5
// baseline (speedup 1.0000x reference)
#include <cuda_runtime.h>

#define H    64
#define G    256     // 4*H
#define F    5
#define BS   28      // samples per block (even); grid=147 -> 1 CTA/SM, single wave
#define NSP  (BS/2)  // sample pairs = 14
#define TPB  256     // one thread per gate row
#define RB   128
#define CPT  (BS * H / TPB)   // cells per thread in phase 2 = 7

typedef unsigned long long ull;

__device__ float g_rank_part[RB];
__device__ float g_reg_part[2];

__device__ __forceinline__ float tanh_hw(float x) {
    float y;
    asm("tanh.approx.f32 %0, %1;" : "=f"(y) : "f"(x));
    return y;
}
__device__ __forceinline__ float sig_hw(float x) {
    return fmaf(tanh_hw(0.5f * x), 0.5f, 0.5f);
}

// packed dual-FMA (sm_103a FFMA2): lanes carry two different SAMPLES
__device__ __forceinline__ ull fma2(ull a, ull b, ull c) {
    ull d;
    asm("fma.rn.f32x2 %0, %1, %2, %3;" : "=l"(d) : "l"(a), "l"(b), "l"(c));
    return d;
}
__device__ __forceinline__ ull pack2(float lo, float hi) {
    return (ull)__float_as_uint(lo) | ((ull)__float_as_uint(hi) << 32);
}
__device__ __forceinline__ float f2lo(ull v) { return __uint_as_float((unsigned)v); }
__device__ __forceinline__ float f2hi(ull v) { return __uint_as_float((unsigned)(v >> 32)); }

__global__ __launch_bounds__(TPB, 1)
void lstm_kernel(const float* __restrict__ feature,
                 const float* __restrict__ Wih, const float* __restrict__ Whh,
                 const float* __restrict__ bih, const float* __restrict__ bhh,
                 const float* __restrict__ Wd,  const float* __restrict__ bd,
                 float* __restrict__ pred, int N, int T)
{
    const int r  = threadIdx.x;          // gate row 0..255 (i,f,g,o blocks of 64)
    const int n0 = blockIdx.x * BS;

    // Whh row duplicated into both f32x2 halves: wdup[k] = (w[k], w[k])  (128 regs)
    ull wdup[H];
    {
        const float4* w4 = (const float4*)(Whh + r * H);
#pragma unroll
        for (int q = 0; q < H / 4; q++) {
            float4 v = w4[q];
            wdup[4 * q + 0] = pack2(v.x, v.x);
            wdup[4 * q + 1] = pack2(v.y, v.y);
            wdup[4 * q + 2] = pack2(v.z, v.z);
            wdup[4 * q + 3] = pack2(v.w, v.w);
        }
    }
    ull widup[F];
#pragma unroll
    for (int f = 0; f < F; f++) { float w = Wih[r * F + f]; widup[f] = pack2(w, w); }
    const ull bias2 = pack2(bih[r] + bhh[r], bih[r] + bhh[r]);

    // h in sample-pair-interleaved layout: hp[sp][k][par]  (par = s&1)
    __shared__ __align__(16) float hp[NSP][H][2];
    __shared__ float g_sm[BS][G];
    __shared__ __align__(8) float xp[2][NSP][F][2];   // pair-interleaved features

    float c_reg[CPT];
#pragma unroll
    for (int u = 0; u < CPT; u++) {
        c_reg[u] = 0.f;
        int idx = r + TPB * u;                 // cell = s*H + j
        int s = idx >> 6, j = idx & 63;
        hp[s >> 1][j][s & 1] = 0.f;
    }
    if (r < BS * F) {
        int s = r / F, f = r % F;
        xp[0][s >> 1][f][s & 1] = 0.f;
        xp[1][s >> 1][f][s & 1] = 0.f;
    }
    __syncthreads();
    if (r < BS * F) {
        int s = r / F, f = r % F;
        if (n0 + s < N) xp[0][s >> 1][f][s & 1] = feature[(size_t)(n0 + s) * T * F + f];
    }
    __syncthreads();

    for (int t = 0; t < T; t++) {
        const int buf = t & 1;

        // ---- phase 1: gates for both samples of each pair in one FFMA2 stream
        // one LDS.128 of hp[sp] covers (k,s0),(k,s1),(k+1,s0),(k+1,s1)
#pragma unroll
        for (int sp = 0; sp < NSP; sp++) {
            ull acc = bias2;
            const ulonglong2* h2 = (const ulonglong2*)hp[sp];   // uniform -> broadcast
#pragma unroll
            for (int q = 0; q < H / 2; q++) {
                ulonglong2 hv = h2[q];
                acc = fma2(wdup[2 * q + 0], hv.x, acc);
                acc = fma2(wdup[2 * q + 1], hv.y, acc);
            }
            const ull* x2 = (const ull*)xp[buf][sp];
#pragma unroll
            for (int f = 0; f < F; f++) acc = fma2(widup[f], x2[f], acc);
            g_sm[2 * sp + 0][r] = f2lo(acc);
            g_sm[2 * sp + 1][r] = f2hi(acc);
        }
        __syncthreads();

        // ---- prefetch x for t+1
        if (t + 1 < T && r < BS * F) {
            int s = r / F, f = r % F;
            if (n0 + s < N)
                xp[buf ^ 1][s >> 1][f][s & 1] =
                    feature[(size_t)(n0 + s) * T * F + (size_t)(t + 1) * F + f];
        }

        // ---- phase 2: LSTM cell update (gate order i,f,g,o), 1792 cells, 7/thread
#pragma unroll
        for (int u = 0; u < CPT; u++) {
            int idx = r + TPB * u;
            int s = idx >> 6, j = idx & 63;
            float ig = sig_hw(g_sm[s][j]);
            float fg = sig_hw(g_sm[s][H + j]);
            float gg = tanh_hw(g_sm[s][2 * H + j]);
            float og = sig_hw(g_sm[s][3 * H + j]);
            float c  = fg * c_reg[u] + ig * gg;
            c_reg[u] = c;
            hp[s >> 1][j][s & 1] = og * tanh_hw(c);
        }
        __syncthreads();
    }

    // ---- head: pred = leaky_relu(h . Wd + bd, 0.2); warps stride samples
    int w = r >> 5, lane = r & 31;
    for (int s = w; s < BS; s += TPB / 32) {
        if (n0 + s < N) {
            int sp = s >> 1, par = s & 1;
            float p = hp[sp][lane][par] * Wd[lane] + hp[sp][lane + 32][par] * Wd[lane + 32];
#pragma unroll
            for (int off = 16; off; off >>= 1) p += __shfl_down_sync(0xffffffffu, p, off);
            if (lane == 0) {
                p += bd[0];
                p = p > 0.f ? p : 0.2f * p;
                pred[n0 + s] = p;
            }
        }
    }
}

// Pairwise rank loss partials + masked MSE partials (deterministic, no atomics).
__global__ void pair_kernel(const float* __restrict__ pred, const float* __restrict__ ret,
                            const unsigned* __restrict__ mask, int N)
{
    __shared__ float p_sm[4096];
    __shared__ float t_sm[4096];
    __shared__ unsigned char m_sm[4096];
    __shared__ float red[256];
    const int tid = threadIdx.x;

    for (int n = tid; n < N; n += blockDim.x) {
        p_sm[n] = pred[n];
        t_sm[n] = ret[n];
        m_sm[n] = (mask[n] != 0u) ? 1 : 0;
    }
    __syncthreads();

    float rsum = 0.f;
    for (int i = blockIdx.x; i < N; i += gridDim.x) {
        if (!m_sm[i]) continue;
        float pi = p_sm[i], gi = t_sm[i];
        for (int j = tid; j < N; j += blockDim.x) {
            float v = -(p_sm[j] - pi) * (t_sm[j] - gi);
            v = fmaxf(v, 0.f);
            rsum += v * (float)m_sm[j];
        }
    }
    red[tid] = rsum;
    __syncthreads();
    for (int s = 128; s; s >>= 1) { if (tid < s) red[tid] += red[tid + s]; __syncthreads(); }
    if (tid == 0) g_rank_part[blockIdx.x] = red[0];

    if (blockIdx.x == 0) {
        float ssq = 0.f, sm = 0.f;
        for (int n = tid; n < N; n += blockDim.x) {
            float m = (float)m_sm[n];
            float d = p_sm[n] - t_sm[n];
            ssq += d * d * m;
            sm  += m;
        }
        __syncthreads();
        red[tid] = ssq; __syncthreads();
        for (int s = 128; s; s >>= 1) { if (tid < s) red[tid] += red[tid + s]; __syncthreads(); }
        if (tid == 0) g_reg_part[0] = red[0];
        __syncthreads();
        red[tid] = sm; __syncthreads();
        for (int s = 128; s; s >>= 1) { if (tid < s) red[tid] += red[tid + s]; __syncthreads(); }
        if (tid == 0) g_reg_part[1] = red[0];
    }
}

__global__ void finalize_kernel(float* __restrict__ out, int N)
{
    if (threadIdx.x == 0 && blockIdx.x == 0) {
        float srank = 0.f;
        for (int b = 0; b < RB; b++) srank += g_rank_part[b];
        float reg  = g_reg_part[0] / (g_reg_part[1] + 1e-8f);
        float rank = srank / ((float)N * (float)N);
        out[N]     = reg + rank;
        out[N + 1] = reg;
        out[N + 2] = rank;
    }
}

extern "C" void kernel_launch(void* const* d_in, const int* in_sizes, int n_in,
                              void* d_out, int out_size)
{
    const float*    feature = (const float*)d_in[0];
    const float*    ret     = (const float*)d_in[1];
    const unsigned* mask    = (const unsigned*)d_in[2];
    const float*    Wih     = (const float*)d_in[3];
    const float*    Whh     = (const float*)d_in[4];
    const float*    bih     = (const float*)d_in[5];
    const float*    bhh     = (const float*)d_in[6];
    const float*    Wd      = (const float*)d_in[7];
    const float*    bd      = (const float*)d_in[8];
    float* out = (float*)d_out;

    const int N = in_sizes[1];                 // 4096
    const int T = in_sizes[0] / (N * F);       // 512

    const int grid = (N + BS - 1) / BS;        // 147
    lstm_kernel<<<grid, TPB>>>(feature, Wih, Whh, bih, bhh, Wd, bd, out, N, T);
    pair_kernel<<<RB, 256>>>(out, ret, mask, N);
    finalize_kernel<<<1, 32>>>(out, N);
}